// round 2
// baseline (speedup 1.0000x reference)
#include <cuda_runtime.h>
#include <cstdint>

// ---------------- problem constants ----------------
#define NMAX   200000
#define CCH    64
#define KTAPS  9
#define TN     128          // rows per block
#define NTHR   128          // threads per block
#define LEAK   0.01f
#define EPS_BN 1e-5f
#define ASTRIDE 128         // sAT channel stride (rows) — conflict-free (broadcast phases)

// dynamic smem layout (floats):
//   sAT: [64][ASTRIDE]           = 8192
//   sB : [64][64]                = 4096
//   sAff: [128]                  = 128
#define SM_AT   0
#define SM_B    (64 * ASTRIDE)
#define SM_AFF  (SM_B + 64 * 64)
#define SM_FLOATS (SM_AFF + 128)          // 12416 floats = 49664 B

// ---------------- scratch (no cudaMalloc allowed) ----------------
__device__ float g_bufA[(size_t)NMAX * CCH];
__device__ float g_bufB[(size_t)NMAX * CCH];
__device__ float g_sums [4][CCH];
__device__ float g_sumsq[4][CCH];
__device__ float g_scale[4][CCH];
__device__ float g_shift[4][CCH];

// ---------------- packed f32x2 helpers ----------------
__device__ __forceinline__ unsigned long long pk2(float lo, float hi) {
    unsigned long long r;
    asm("mov.b64 %0, {%1, %2};" : "=l"(r) : "f"(lo), "f"(hi));
    return r;
}
__device__ __forceinline__ void upk2(float &lo, float &hi, unsigned long long v) {
    asm("mov.b64 {%0, %1}, %2;" : "=f"(lo), "=f"(hi) : "l"(v));
}
__device__ __forceinline__ void fma2(unsigned long long &d,
                                     unsigned long long a, unsigned long long b) {
    asm("fma.rn.f32x2 %0, %1, %2, %0;" : "+l"(d) : "l"(a), "l"(b));
}

// ---------------- kernels ----------------
__global__ void zero_stats_k() {
    int i = threadIdx.x;
    if (i < 4 * CCH) {
        ((float*)g_sums)[i]  = 0.f;
        ((float*)g_sumsq)[i] = 0.f;
    }
}

// conv + leaky + per-channel stats. If AFFINE, applies y = x*scale + shift
// (BN of previous stage) to gathered features; pad rows stay exactly 0.
template <bool AFFINE>
__global__ __launch_bounds__(NTHR)
void conv_k(const float* __restrict__ src,
            const int*   __restrict__ nbr,
            const float* __restrict__ w,
            float*       __restrict__ dst,
            int nTotal, int stage, int affStage)
{
    extern __shared__ float smem[];
    float* sAT  = smem + SM_AT;     // [64][ASTRIDE] transposed A tile
    float* sB   = smem + SM_B;      // [64c][64o] weights
    float* sAff = smem + SM_AFF;    // [64 scale][64 shift]

    const int tid   = threadIdx.x;
    const int lane8 = tid & 7;        // col group
    const int rg    = tid >> 3;       // row group (0..15)
    const int r0    = rg * 8;
    const int nBase = blockIdx.x * TN;

    if (AFFINE) {
        sAff[tid] = (tid < 64) ? g_scale[affStage][tid]
                               : g_shift[affStage][tid - 64];
    }

    unsigned long long acc[4][8];
#pragma unroll
    for (int rr = 0; rr < 4; ++rr)
#pragma unroll
        for (int j = 0; j < 8; ++j) acc[rr][j] = 0ull;

    for (int k = 0; k < KTAPS; ++k) {
        __syncthreads();   // smem safe to overwrite (also orders sAff store)

        // ---- gather: one thread per row, transposed store ----
        {
            const int gn   = nBase + tid;
            int nidx = nTotal;                       // pad
            if (gn < nTotal) nidx = nbr[gn * 9 + k];
            const bool pad = (nidx >= nTotal);
            const float4* srow = (const float4*)(src + (size_t)nidx * CCH);
#pragma unroll
            for (int c4 = 0; c4 < 16; ++c4) {
                float4 v = make_float4(0.f, 0.f, 0.f, 0.f);
                if (!pad) {
                    v = srow[c4];
                    if (AFFINE) {
                        const int c = c4 * 4;
                        v.x = fmaf(v.x, sAff[c + 0], sAff[64 + c + 0]);
                        v.y = fmaf(v.y, sAff[c + 1], sAff[64 + c + 1]);
                        v.z = fmaf(v.z, sAff[c + 2], sAff[64 + c + 2]);
                        v.w = fmaf(v.w, sAff[c + 3], sAff[64 + c + 3]);
                    }
                }
                const int c = c4 * 4;
                sAT[(c + 0) * ASTRIDE + tid] = v.x;
                sAT[(c + 1) * ASTRIDE + tid] = v.y;
                sAT[(c + 2) * ASTRIDE + tid] = v.z;
                sAT[(c + 3) * ASTRIDE + tid] = v.w;
            }
        }
        // ---- weights for tap k: [64c][64o] contiguous copy ----
        {
            const float4* wk = (const float4*)(w + (size_t)k * CCH * CCH);
#pragma unroll
            for (int t = 0; t < 8; ++t) {
                const int i4 = tid + t * NTHR;       // 0..1023
                *(float4*)&sB[i4 * 4] = wk[i4];
            }
        }
        __syncthreads();

        // ---- 128x64x64 tile MAC with packed f32x2 ----
#pragma unroll 4
        for (int c = 0; c < 64; ++c) {
            const float4 aL = *(const float4*)&sAT[c * ASTRIDE + r0];
            const float4 aH = *(const float4*)&sAT[c * ASTRIDE + r0 + 4];
            unsigned long long a2[4];
            a2[0] = pk2(aL.x, aL.y);
            a2[1] = pk2(aL.z, aL.w);
            a2[2] = pk2(aH.x, aH.y);
            a2[3] = pk2(aH.z, aH.w);
            const float* bc = &sB[c * 64 + lane8];
#pragma unroll
            for (int j = 0; j < 8; ++j) {
                const float bs = bc[8 * j];
                const unsigned long long b2 = pk2(bs, bs);
                fma2(acc[0][j], a2[0], b2);
                fma2(acc[1][j], a2[1], b2);
                fma2(acc[2][j], a2[2], b2);
                fma2(acc[3][j], a2[3], b2);
            }
        }
    }

    // ---- epilogue: leaky relu, store, per-channel stats ----
    __syncthreads();
    float s[8], s2[8];
#pragma unroll
    for (int j = 0; j < 8; ++j) { s[j] = 0.f; s2[j] = 0.f; }

#pragma unroll
    for (int rr = 0; rr < 4; ++rr) {
#pragma unroll
        for (int j = 0; j < 8; ++j) {
            float lo, hi;
            upk2(lo, hi, acc[rr][j]);
            lo = (lo > 0.f) ? lo : LEAK * lo;
            hi = (hi > 0.f) ? hi : LEAK * hi;
            const int col  = lane8 + 8 * j;
            const int rowL = nBase + r0 + 2 * rr;
            if (rowL     < nTotal) dst[(size_t)rowL * CCH + col]       = lo;
            if (rowL + 1 < nTotal) dst[(size_t)(rowL + 1) * CCH + col] = hi;
            // out-of-range rows gathered zeros -> lo/hi == 0, safe to accumulate
            s[j]  += lo + hi;
            s2[j] += lo * lo + hi * hi;
        }
    }

    float* sRed = sAT;   // reuse: [16][64] sums, +1024 sumsq
#pragma unroll
    for (int j = 0; j < 8; ++j) {
        const int col = lane8 + 8 * j;
        sRed[rg * 64 + col]        = s[j];
        sRed[1024 + rg * 64 + col] = s2[j];
    }
    __syncthreads();
    if (tid < 64) {
        float ts = 0.f, ts2 = 0.f;
#pragma unroll
        for (int g = 0; g < 16; ++g) {
            ts  += sRed[g * 64 + tid];
            ts2 += sRed[1024 + g * 64 + tid];
        }
        atomicAdd(&g_sums[stage][tid], ts);
        atomicAdd(&g_sumsq[stage][tid], ts2);
    }
}

__global__ void bn_coeff_k(int stage, const float* __restrict__ gamma,
                           const float* __restrict__ beta, float invN) {
    const int ch = threadIdx.x;
    if (ch >= CCH) return;
    const float m = g_sums[stage][ch] * invN;
    const float v = g_sumsq[stage][ch] * invN - m * m;
    const float a = gamma[ch] * rsqrtf(v + EPS_BN);
    g_scale[stage][ch] = a;
    g_shift[stage][ch] = beta[ch] - m * a;
}

// out = BN3(y4) + BN1(y2); out buffer already holds y4
__global__ void final_k(float* __restrict__ out, const float* __restrict__ y2,
                        int total4) {
    const int i = blockIdx.x * blockDim.x + threadIdx.x;
    if (i >= total4) return;
    float4 a = ((float4*)out)[i];
    const float4 b = ((const float4*)y2)[i];
    const int c = (i * 4) & 63;
    a.x = fmaf(a.x, g_scale[3][c + 0], g_shift[3][c + 0]) +
          fmaf(b.x, g_scale[1][c + 0], g_shift[1][c + 0]);
    a.y = fmaf(a.y, g_scale[3][c + 1], g_shift[3][c + 1]) +
          fmaf(b.y, g_scale[1][c + 1], g_shift[1][c + 1]);
    a.z = fmaf(a.z, g_scale[3][c + 2], g_shift[3][c + 2]) +
          fmaf(b.z, g_scale[1][c + 2], g_shift[1][c + 2]);
    a.w = fmaf(a.w, g_scale[3][c + 3], g_shift[3][c + 3]) +
          fmaf(b.w, g_scale[1][c + 3], g_shift[1][c + 3]);
    ((float4*)out)[i] = a;
}

// ---------------- launcher ----------------
extern "C" void kernel_launch(void* const* d_in, const int* in_sizes, int n_in,
                              void* d_out, int out_size)
{
    const float* features = (const float*)d_in[0];
    const float* w1   = (const float*)d_in[1];
    const float* w1_2 = (const float*)d_in[2];
    const float* w2   = (const float*)d_in[3];
    const float* w3   = (const float*)d_in[4];
    const float* g0   = (const float*)d_in[5];
    const float* b0   = (const float*)d_in[6];
    const float* g0_2 = (const float*)d_in[7];
    const float* b0_2 = (const float*)d_in[8];
    const float* g1   = (const float*)d_in[9];
    const float* b1   = (const float*)d_in[10];
    const float* g2   = (const float*)d_in[11];
    const float* b2   = (const float*)d_in[12];
    const int*   nbr13 = (const int*)d_in[13];
    const int*   nbr31 = (const int*)d_in[14];

    const int nTotal = in_sizes[0] / CCH;
    const float invN = 1.0f / (float)nTotal;
    const int grid   = (nTotal + TN - 1) / TN;
    const int smemB  = SM_FLOATS * (int)sizeof(float);

    cudaFuncSetAttribute(conv_k<false>, cudaFuncAttributeMaxDynamicSharedMemorySize, smemB);
    cudaFuncSetAttribute(conv_k<true >, cudaFuncAttributeMaxDynamicSharedMemorySize, smemB);

    float *bufA = nullptr, *bufB = nullptr;
    cudaGetSymbolAddress((void**)&bufA, g_bufA);
    cudaGetSymbolAddress((void**)&bufB, g_bufB);
    float* out = (float*)d_out;

    zero_stats_k<<<1, 512>>>();

    // shortcut branch: conv(nbr13,w1) -> BN0 -> conv(nbr31,w1_2) -> BN1
    conv_k<false><<<grid, NTHR, smemB>>>(features, nbr13, w1, bufA, nTotal, 0, 0);
    bn_coeff_k<<<1, 64>>>(0, g0, b0, invN);
    conv_k<true ><<<grid, NTHR, smemB>>>(bufA, nbr31, w1_2, bufB, nTotal, 1, 0);
    bn_coeff_k<<<1, 64>>>(1, g0_2, b0_2, invN);

    // main branch: conv(nbr31,w2) -> BN2 -> conv(nbr13,w3) -> BN3
    conv_k<false><<<grid, NTHR, smemB>>>(features, nbr31, w2, bufA, nTotal, 2, 0);
    bn_coeff_k<<<1, 64>>>(2, g1, b1, invN);
    conv_k<true ><<<grid, NTHR, smemB>>>(bufA, nbr13, w3, out, nTotal, 3, 2);
    bn_coeff_k<<<1, 64>>>(3, g2, b2, invN);

    // out = BN3(out) + BN1(bufB)
    const int total4 = nTotal * CCH / 4;
    final_k<<<(total4 + 255) / 256, 256>>>(out, bufB, total4);
}

// round 4
// speedup vs baseline: 2.8587x; 2.8587x over previous
#include <cuda_runtime.h>
#include <cuda_bf16.h>
#include <cstdint>

// ---------------- problem constants ----------------
#define NMAX   200000
#define CCH    64
#define KTAPS  9
#define TN     128          // rows per block (MMA M)
#define NTHR   128
#define LEAK   0.01f
#define EPS_BN 1e-5f

// dynamic smem plane offsets (bytes): A hi/lo [128][64]bf16, B hi/lo [64][64]bf16
#define OFF_AHI 0
#define OFF_ALO 16384
#define OFF_BHI 32768
#define OFF_BLO 40960
#define DSM_BYTES 49152
#define SC_STRIDE 68        // epilogue fp32 tile stride (floats)

// ---------------- scratch (no cudaMalloc allowed) ----------------
__device__ float g_bufA[(size_t)NMAX * CCH];
__device__ float g_bufB[(size_t)NMAX * CCH];
__device__ __nv_bfloat16 g_wHi[4 * KTAPS * 64 * 64];  // [tensor][tap][o][c]
__device__ __nv_bfloat16 g_wLo[4 * KTAPS * 64 * 64];
__device__ float g_sums [4][CCH];
__device__ float g_sumsq[4][CCH];
__device__ float g_scale[4][CCH];
__device__ float g_shift[4][CCH];

// ---------------- helpers ----------------
__device__ __forceinline__ uint32_t smem_u32(const void* p) {
    uint32_t a;
    asm("{ .reg .u64 t; cvta.to.shared.u64 t, %1; cvt.u32.u64 %0, t; }" : "=r"(a) : "l"(p));
    return a;
}
__device__ __forceinline__ void ldsm4(uint32_t* r, uint32_t addr) {
    asm volatile("ldmatrix.sync.aligned.m8n8.x4.shared.b16 {%0,%1,%2,%3}, [%4];"
        : "=r"(r[0]), "=r"(r[1]), "=r"(r[2]), "=r"(r[3]) : "r"(addr));
}
__device__ __forceinline__ void mma16816(float* c, const uint32_t* a, const uint32_t* b) {
    asm volatile("mma.sync.aligned.m16n8k16.row.col.f32.bf16.bf16.f32 "
        "{%0,%1,%2,%3}, {%4,%5,%6,%7}, {%8,%9}, {%0,%1,%2,%3};"
        : "+f"(c[0]), "+f"(c[1]), "+f"(c[2]), "+f"(c[3])
        : "r"(a[0]), "r"(a[1]), "r"(a[2]), "r"(a[3]), "r"(b[0]), "r"(b[1]));
}
__device__ __forceinline__ void bsplit(float v, uint16_t &h, uint16_t &l) {
    __nv_bfloat16 bh = __float2bfloat16(v);
    h = __bfloat16_as_ushort(bh);
    float r = v - __bfloat162float(bh);
    l = __bfloat16_as_ushort(__float2bfloat16(r));
}

// ---------------- aux kernels ----------------
__global__ void zero_stats_k() {
    int i = threadIdx.x;
    if (i < 4 * CCH) { ((float*)g_sums)[i] = 0.f; ((float*)g_sumsq)[i] = 0.f; }
}

// weights [9][c][o] -> [tensor][tap][o][c] bf16 hi/lo planes
__global__ void prep_w_k(const float* __restrict__ w0, const float* __restrict__ w1,
                         const float* __restrict__ w2, const float* __restrict__ w3) {
    const int t = blockIdx.x / KTAPS, k = blockIdx.x % KTAPS;
    const float* w = (t == 0) ? w0 : (t == 1) ? w1 : (t == 2) ? w2 : w3;
    const float* src = w + k * 4096;
    __nv_bfloat16* dh = g_wHi + (size_t)(t * KTAPS + k) * 4096;
    __nv_bfloat16* dl = g_wLo + (size_t)(t * KTAPS + k) * 4096;
#pragma unroll
    for (int i = 0; i < 16; ++i) {
        const int j = threadIdx.x + i * 256;     // j = o*64 + c
        const int o = j >> 6, c = j & 63;
        const float v = src[c * 64 + o];
        __nv_bfloat16 bh = __float2bfloat16(v);
        dh[j] = bh;
        dl[j] = __float2bfloat16(v - __bfloat162float(bh));
    }
}

// ---------------- main conv kernel (mma.sync bf16, 3-term) ----------------
template <bool AFFINE>
__global__ __launch_bounds__(NTHR)
void conv_mma_k(const float* __restrict__ src, const int* __restrict__ nbr,
                int wtIdx, float* __restrict__ dst, int nTotal, int stage, int affStage)
{
    extern __shared__ char smemc[];
    __shared__ float sAff[128];

    const int tid   = threadIdx.x;
    const int lane  = tid & 31;
    const int wid   = tid >> 5;
    const int nBase = blockIdx.x * TN;
    const bool rowOK = (nBase + tid) < nTotal;

    if (AFFINE)
        sAff[tid] = (tid < 64) ? g_scale[affStage][tid] : g_shift[affStage][tid - 64];

    const uint32_t sbase = smem_u32(smemc);
    const int rowBase = wid * 32;
    const int lsw = lane & 7, l15 = lane & 15, l16 = lane >> 4;

    float C[2][8][4];
#pragma unroll
    for (int mt = 0; mt < 2; ++mt)
#pragma unroll
        for (int nt = 0; nt < 8; ++nt)
#pragma unroll
            for (int i = 0; i < 4; ++i) C[mt][nt][i] = 0.f;

    const __nv_bfloat16* wHiT = g_wHi + (size_t)(wtIdx * KTAPS) * 4096;
    const __nv_bfloat16* wLoT = g_wLo + (size_t)(wtIdx * KTAPS) * 4096;

    for (int k = 0; k < KTAPS; ++k) {
        __syncthreads();   // prior tap's ldmatrix reads done

        // ---- gather A row (thread = row), affine-fold, bf16 hi/lo split ----
        {
            int nidx = nTotal;
            if (rowOK) nidx = nbr[(size_t)(nBase + tid) * KTAPS + k];
            const bool pad = (nidx >= nTotal);
            const float4* arow = (const float4*)(src + (size_t)nidx * CCH);
            char* aHiRow = smemc + OFF_AHI + tid * 128;
            char* aLoRow = smemc + OFF_ALO + tid * 128;
            const int rsw = tid & 7;
#pragma unroll
            for (int g = 0; g < 8; ++g) {
                float4 v0 = make_float4(0.f, 0.f, 0.f, 0.f);
                float4 v1 = make_float4(0.f, 0.f, 0.f, 0.f);
                if (!pad) {
                    v0 = arow[2 * g];
                    v1 = arow[2 * g + 1];
                    if (AFFINE) {
                        const int c = g * 8;
                        v0.x = fmaf(v0.x, sAff[c + 0], sAff[64 + c + 0]);
                        v0.y = fmaf(v0.y, sAff[c + 1], sAff[64 + c + 1]);
                        v0.z = fmaf(v0.z, sAff[c + 2], sAff[64 + c + 2]);
                        v0.w = fmaf(v0.w, sAff[c + 3], sAff[64 + c + 3]);
                        v1.x = fmaf(v1.x, sAff[c + 4], sAff[64 + c + 4]);
                        v1.y = fmaf(v1.y, sAff[c + 5], sAff[64 + c + 5]);
                        v1.z = fmaf(v1.z, sAff[c + 6], sAff[64 + c + 6]);
                        v1.w = fmaf(v1.w, sAff[c + 7], sAff[64 + c + 7]);
                    }
                }
                uint16_t h[8], l[8];
                bsplit(v0.x, h[0], l[0]); bsplit(v0.y, h[1], l[1]);
                bsplit(v0.z, h[2], l[2]); bsplit(v0.w, h[3], l[3]);
                bsplit(v1.x, h[4], l[4]); bsplit(v1.y, h[5], l[5]);
                bsplit(v1.z, h[6], l[6]); bsplit(v1.w, h[7], l[7]);
                uint4 H, L;
                H.x = (uint32_t)h[0] | ((uint32_t)h[1] << 16);
                H.y = (uint32_t)h[2] | ((uint32_t)h[3] << 16);
                H.z = (uint32_t)h[4] | ((uint32_t)h[5] << 16);
                H.w = (uint32_t)h[6] | ((uint32_t)h[7] << 16);
                L.x = (uint32_t)l[0] | ((uint32_t)l[1] << 16);
                L.y = (uint32_t)l[2] | ((uint32_t)l[3] << 16);
                L.z = (uint32_t)l[4] | ((uint32_t)l[5] << 16);
                L.w = (uint32_t)l[6] | ((uint32_t)l[7] << 16);
                const int off = (g ^ rsw) << 4;
                *(uint4*)(aHiRow + off) = H;
                *(uint4*)(aLoRow + off) = L;
            }
        }
        // ---- B planes [n=o][k=c] bf16, swizzled ----
        {
            const __nv_bfloat16* bh = wHiT + (size_t)k * 4096;
            const __nv_bfloat16* bl = wLoT + (size_t)k * 4096;
#pragma unroll
            for (int i = 0; i < 4; ++i) {
                const int id = tid * 4 + i;          // 0..511 16B chunks
                const int n = id >> 3, kg = id & 7;
                const int srcOff = n * 64 + kg * 8;
                const int dstOff = n * 128 + ((kg ^ (n & 7)) << 4);
                *(uint4*)(smemc + OFF_BHI + dstOff) = *(const uint4*)(bh + srcOff);
                *(uint4*)(smemc + OFF_BLO + dstOff) = *(const uint4*)(bl + srcOff);
            }
        }
        __syncthreads();

        // ---- 4 k16 chunks: ldmatrix + 48 MMAs each ----
#pragma unroll
        for (int q = 0; q < 4; ++q) {
            const int kg = 2 * q + l16;
            uint32_t ah[2][4], al[2][4];
#pragma unroll
            for (int mt = 0; mt < 2; ++mt) {
                const uint32_t off =
                    (uint32_t)((rowBase + mt * 16 + l15) * 128 + ((kg ^ lsw) << 4));
                ldsm4(ah[mt], sbase + OFF_AHI + off);
                ldsm4(al[mt], sbase + OFF_ALO + off);
            }
            uint32_t bh[8][2], bl[8][2];
#pragma unroll
            for (int p = 0; p < 4; ++p) {
                const uint32_t off =
                    (uint32_t)((16 * p + l15) * 128 + ((kg ^ lsw) << 4));
                uint32_t r[4];
                ldsm4(r, sbase + OFF_BHI + off);
                bh[2*p][0] = r[0]; bh[2*p+1][0] = r[1];
                bh[2*p][1] = r[2]; bh[2*p+1][1] = r[3];
                ldsm4(r, sbase + OFF_BLO + off);
                bl[2*p][0] = r[0]; bl[2*p+1][0] = r[1];
                bl[2*p][1] = r[2]; bl[2*p+1][1] = r[3];
            }
#pragma unroll
            for (int mt = 0; mt < 2; ++mt)
#pragma unroll
                for (int nt = 0; nt < 8; ++nt) {
                    mma16816(C[mt][nt], ah[mt], bh[nt]);
                    mma16816(C[mt][nt], ah[mt], bl[nt]);
                    mma16816(C[mt][nt], al[mt], bh[nt]);
                }
        }
    }

    // ---- epilogue: leaky on frags -> smem fp32 tile -> store + stats ----
    __syncthreads();
    float* sC = (float*)smemc;                   // [128][SC_STRIDE]
    const int fg = lane >> 2, ft2 = (lane & 3) * 2;
#pragma unroll
    for (int mt = 0; mt < 2; ++mt)
#pragma unroll
        for (int nt = 0; nt < 8; ++nt) {
            float* c = C[mt][nt];
#pragma unroll
            for (int i = 0; i < 4; ++i)
                c[i] = (c[i] > 0.f) ? c[i] : LEAK * c[i];
            const int r0 = rowBase + mt * 16 + fg;
            const int col = nt * 8 + ft2;
            *(float2*)&sC[r0 * SC_STRIDE + col]       = make_float2(c[0], c[1]);
            *(float2*)&sC[(r0 + 8) * SC_STRIDE + col] = make_float2(c[2], c[3]);
        }
    __syncthreads();

    if (rowOK) {
        float4* drow = (float4*)(dst + (size_t)(nBase + tid) * CCH);
        const float4* rowp = (const float4*)(sC + tid * SC_STRIDE);
#pragma unroll
        for (int c4 = 0; c4 < 16; ++c4) drow[c4] = rowp[c4];
    }

    {
        const int ch = tid >> 1, half = tid & 1;
        float s = 0.f, s2 = 0.f;
#pragma unroll 8
        for (int i = 0; i < 64; ++i) {
            const float v = sC[(half * 64 + i) * SC_STRIDE + ch];
            s += v; s2 += v * v;
        }
        s  += __shfl_xor_sync(0xffffffffu, s, 1);
        s2 += __shfl_xor_sync(0xffffffffu, s2, 1);
        if (!half) {
            atomicAdd(&g_sums[stage][ch], s);
            atomicAdd(&g_sumsq[stage][ch], s2);
        }
    }
}

__global__ void bn_coeff_k(int stage, const float* __restrict__ gamma,
                           const float* __restrict__ beta, float invN) {
    const int ch = threadIdx.x;
    if (ch >= CCH) return;
    const float m = g_sums[stage][ch] * invN;
    const float v = g_sumsq[stage][ch] * invN - m * m;
    const float a = gamma[ch] * rsqrtf(v + EPS_BN);
    g_scale[stage][ch] = a;
    g_shift[stage][ch] = beta[ch] - m * a;
}

__global__ void final_k(float* __restrict__ out, const float* __restrict__ y2,
                        int total4) {
    const int i = blockIdx.x * blockDim.x + threadIdx.x;
    if (i >= total4) return;
    float4 a = ((float4*)out)[i];
    const float4 b = ((const float4*)y2)[i];
    const int c = (i * 4) & 63;
    a.x = fmaf(a.x, g_scale[3][c + 0], g_shift[3][c + 0]) +
          fmaf(b.x, g_scale[1][c + 0], g_shift[1][c + 0]);
    a.y = fmaf(a.y, g_scale[3][c + 1], g_shift[3][c + 1]) +
          fmaf(b.y, g_scale[1][c + 1], g_shift[1][c + 1]);
    a.z = fmaf(a.z, g_scale[3][c + 2], g_shift[3][c + 2]) +
          fmaf(b.z, g_scale[1][c + 2], g_shift[1][c + 2]);
    a.w = fmaf(a.w, g_scale[3][c + 3], g_shift[3][c + 3]) +
          fmaf(b.w, g_scale[1][c + 3], g_shift[1][c + 3]);
    ((float4*)out)[i] = a;
}

// ---------------- launcher ----------------
extern "C" void kernel_launch(void* const* d_in, const int* in_sizes, int n_in,
                              void* d_out, int out_size)
{
    const float* features = (const float*)d_in[0];
    const float* w1   = (const float*)d_in[1];
    const float* w1_2 = (const float*)d_in[2];
    const float* w2   = (const float*)d_in[3];
    const float* w3   = (const float*)d_in[4];
    const float* g0   = (const float*)d_in[5];
    const float* b0   = (const float*)d_in[6];
    const float* g0_2 = (const float*)d_in[7];
    const float* b0_2 = (const float*)d_in[8];
    const float* g1   = (const float*)d_in[9];
    const float* b1   = (const float*)d_in[10];
    const float* g2   = (const float*)d_in[11];
    const float* b2   = (const float*)d_in[12];
    const int*   nbr13 = (const int*)d_in[13];
    const int*   nbr31 = (const int*)d_in[14];

    const int nTotal = in_sizes[0] / CCH;
    const float invN = 1.0f / (float)nTotal;
    const int grid   = (nTotal + TN - 1) / TN;

    cudaFuncSetAttribute(conv_mma_k<false>, cudaFuncAttributeMaxDynamicSharedMemorySize, DSM_BYTES);
    cudaFuncSetAttribute(conv_mma_k<true >, cudaFuncAttributeMaxDynamicSharedMemorySize, DSM_BYTES);

    float *bufA = nullptr, *bufB = nullptr;
    cudaGetSymbolAddress((void**)&bufA, g_bufA);
    cudaGetSymbolAddress((void**)&bufB, g_bufB);
    float* out = (float*)d_out;

    prep_w_k<<<4 * KTAPS, 256>>>(w1, w1_2, w2, w3);
    zero_stats_k<<<1, 512>>>();

    // shortcut branch: conv(nbr13,w1) -> BN0 -> conv(nbr31,w1_2) -> BN1
    conv_mma_k<false><<<grid, NTHR, DSM_BYTES>>>(features, nbr13, 0, bufA, nTotal, 0, 0);
    bn_coeff_k<<<1, 64>>>(0, g0, b0, invN);
    conv_mma_k<true ><<<grid, NTHR, DSM_BYTES>>>(bufA, nbr31, 1, bufB, nTotal, 1, 0);
    bn_coeff_k<<<1, 64>>>(1, g0_2, b0_2, invN);

    // main branch: conv(nbr31,w2) -> BN2 -> conv(nbr13,w3) -> BN3
    conv_mma_k<false><<<grid, NTHR, DSM_BYTES>>>(features, nbr31, 2, bufA, nTotal, 2, 0);
    bn_coeff_k<<<1, 64>>>(2, g1, b1, invN);
    conv_mma_k<true ><<<grid, NTHR, DSM_BYTES>>>(bufA, nbr13, 3, out, nTotal, 3, 2);
    bn_coeff_k<<<1, 64>>>(3, g2, b2, invN);

    // out = BN3(out) + BN1(bufB)
    const int total4 = nTotal * CCH / 4;
    final_k<<<(total4 + 255) / 256, 256>>>(out, bufB, total4);
}